// round 9
// baseline (speedup 1.0000x reference)
#include <cuda_runtime.h>

// PWC-Net correlation (MAX_DISP=4 -> 81 channels) + LeakyReLU(0.1), /C normalize.
// feat1, feat2: [N=8, C=256, H=80, W=160] fp32. out: [N, 81, H, W] fp32.
//
// R6: cp.async double-buffer -> 250us. R7: persistent grid -> 232us.
// R8: fma.rn.f32x2 (FFMA2) packed accumulation along dx pairs.
//     R7 floors: FFMA pipe 224Kcyc of 441Kcyc total (the largest), crossbar
//     ~1.3-1.9Kcyc/phase of 1.6K. FFMA2 halves fma-pipe slots (45 -> 25 per
//     channel) at the cost of 17 ALU movs (alu pipe at 9%, ample headroom).
//     Accumulator reg count unchanged (45) -> occupancy preserved.

#define MAXD 4
#define DD   9
#define NCH  81
#define C_   256
#define H_   80
#define W_   160
#define N_   8
#define HW_  (H_ * W_)
#define NROWS (N_ * H_)
#define CC   4
#define P_   5
#define F2W  (W_ + 2*MAXD)   // 168
#define NQ4  (F2W / 4)       // 42
#define NTHREADS (DD * 32)   // 288
#define NCHUNK (C_ / CC)     // 64
#define NBLOCKS 296          // 148 SMs * 2 CTAs

#define S1_FLOATS (2 * CC * W_)
#define S2_FLOATS (2 * CC * DD * F2W)
#define SMEM_BYTES ((S1_FLOATS + S2_FLOATS) * 4)  // 53504 B

__device__ int g_row_ctr;
__global__ void reset_ctr_kernel() { g_row_ctr = 0; }

__device__ __forceinline__ void cp16(float* dst_smem, const float* src_gmem) {
    unsigned d = (unsigned)__cvta_generic_to_shared(dst_smem);
    asm volatile("cp.async.cg.shared.global [%0], [%1], 16;" :: "r"(d), "l"(src_gmem));
}
#define CP_COMMIT() asm volatile("cp.async.commit_group;")
#define CP_WAIT0()  asm volatile("cp.async.wait_group 0;" ::: "memory")

__device__ __forceinline__ unsigned long long pk2(float lo, float hi) {
    unsigned long long r;
    asm("mov.b64 %0, {%1, %2};" : "=l"(r) : "f"(lo), "f"(hi));
    return r;
}
__device__ __forceinline__ void upk2(float& lo, float& hi, unsigned long long v) {
    asm("mov.b64 {%0, %1}, %2;" : "=f"(lo), "=f"(hi) : "l"(v));
}
__device__ __forceinline__ void fma2(unsigned long long& d, unsigned long long a,
                                     unsigned long long b) {
    asm("fma.rn.f32x2 %0, %1, %2, %0;" : "+l"(d) : "l"(a), "l"(b));
}

__global__ __launch_bounds__(NTHREADS, 2)
void corr_leaky_kernel(const float* __restrict__ f1,
                       const float* __restrict__ f2,
                       float* __restrict__ out)
{
    extern __shared__ __align__(16) float smem[];
    float* s1 = smem;               // [2][CC][W_]
    float* s2 = smem + S1_FLOATS;   // [2][CC][DD][F2W]
#define S1REF(b,c,x)   s1[((b)*CC + (c))*W_ + (x)]
#define S2REF(b,c,r,j) s2[(((b)*CC + (c))*DD + (r))*F2W + (j)]
    __shared__ int s_row;

    const int tid  = threadIdx.x;
    const int dy   = tid >> 5;
    const int lane = tid & 31;
    const int x0   = lane * P_;

    const int f1c  = tid / 40;
    const int f1j4 = tid - f1c * 40;
    const bool f1ok = (tid < CC * (W_ / 4));

    const float scale = 1.0f / (float)C_;

    for (;;) {
        if (tid == 0) s_row = atomicAdd(&g_row_ctr, 1);
        __syncthreads();
        const int row = s_row;
        __syncthreads();
        if (row >= NROWS) break;

        const int n = row / H_;
        const int y = row - n * H_;

        const int img_base = n * C_ * HW_;
        const int  gy    = y + dy - MAXD;
        const bool rowok = ((unsigned)gy < (unsigned)H_);
        const float* f1base = f1 + img_base + y * W_;
        const float* f2base = f2 + img_base + gy * W_;

        // pad slots (fixed positions) in both buffers
        const float4 z4 = make_float4(0.f, 0.f, 0.f, 0.f);
#pragma unroll
        for (int b = 0; b < 2; b++)
#pragma unroll
            for (int c = 0; c < CC; c++) {
                if (rowok) {
                    if (lane == 0) *(float4*)&S2REF(b, c, dy, 0) = z4;
                    if (lane == 1) *(float4*)&S2REF(b, c, dy, 4 * (NQ4 - 1)) = z4;
                } else {
                    *(float4*)&S2REF(b, c, dy, 4 * lane) = z4;
                    if (lane < NQ4 - 32) *(float4*)&S2REF(b, c, dy, 4 * (32 + lane)) = z4;
                }
            }

        // packed accumulators: acc2[p][j] = (dx=2j, dx=2j+1); acc8[p] = dx=8
        unsigned long long acc2[P_][4];
        float acc8[P_];
#pragma unroll
        for (int p = 0; p < P_; p++) {
#pragma unroll
            for (int j = 0; j < 4; j++) acc2[p][j] = 0ull;
            acc8[p] = 0.0f;
        }

        // prologue prefetch chunk 0
        if (f1ok) cp16(&S1REF(0, f1c, 4 * f1j4), f1base + f1c * HW_ + 4 * f1j4);
        if (rowok) {
#pragma unroll
            for (int c = 0; c < CC; c++) {
                const float* rowp = f2base + c * HW_;
                if (lane >= 1) cp16(&S2REF(0, c, dy, 4 * lane),        rowp + 4 * lane - 4);
                if (lane <= 8) cp16(&S2REF(0, c, dy, 4 * (32 + lane)), rowp + 4 * (32 + lane) - 4);
            }
        }
        CP_COMMIT();

        for (int i = 0; i < NCHUNK; i++) {
            const int cur = i & 1;
            CP_WAIT0();
            __syncthreads();

            if (i + 1 < NCHUNK) {
                const int nb = cur ^ 1;
                const int c0 = (i + 1) * CC;
                if (f1ok) cp16(&S1REF(nb, f1c, 4 * f1j4),
                               f1base + (c0 + f1c) * HW_ + 4 * f1j4);
                if (rowok) {
#pragma unroll
                    for (int c = 0; c < CC; c++) {
                        const float* rowp = f2base + (c0 + c) * HW_;
                        if (lane >= 1) cp16(&S2REF(nb, c, dy, 4 * lane),        rowp + 4 * lane - 4);
                        if (lane <= 8) cp16(&S2REF(nb, c, dy, 4 * (32 + lane)), rowp + 4 * (32 + lane) - 4);
                    }
                }
                CP_COMMIT();
            }

            // compute on buf[cur]: per channel 18 LDS, 17 packs, 20 FFMA2 + 5 FFMA
#pragma unroll
            for (int cc = 0; cc < CC; cc++) {
                float a[P_];
                float b[P_ + DD - 1];
#pragma unroll
                for (int p = 0; p < P_; p++) a[p] = S1REF(cur, cc, x0 + p);
#pragma unroll
                for (int k = 0; k < P_ + DD - 1; k++) b[k] = S2REF(cur, cc, dy, x0 + k);

                unsigned long long b2[P_ + DD - 2];   // (b[k], b[k+1]) for k=0..11
#pragma unroll
                for (int k = 0; k < P_ + DD - 2; k++) b2[k] = pk2(b[k], b[k + 1]);
#pragma unroll
                for (int p = 0; p < P_; p++) {
                    const unsigned long long a2 = pk2(a[p], a[p]);
#pragma unroll
                    for (int j = 0; j < 4; j++)
                        fma2(acc2[p][j], a2, b2[p + 2 * j]);
                    acc8[p] = fmaf(a[p], b[p + 8], acc8[p]);
                }
            }
        }

        // epilogue: unpack, /C, LeakyReLU(0.1), store
        const int out_base = n * NCH * HW_ + y * W_;
#pragma unroll
        for (int j = 0; j < 4; j++) {
#pragma unroll
            for (int half = 0; half < 2; half++) {
                const int dx = 2 * j + half;
                const int ch = dy * DD + dx;
                float* orow = out + out_base + ch * HW_;
#pragma unroll
                for (int p = 0; p < P_; p++) {
                    float lo, hi;
                    upk2(lo, hi, acc2[p][j]);
                    float v = (half ? hi : lo) * scale;
                    v = (v > 0.0f) ? v : 0.1f * v;
                    orow[x0 + p] = v;
                }
            }
        }
        {
            const int ch = dy * DD + 8;
            float* orow = out + out_base + ch * HW_;
#pragma unroll
            for (int p = 0; p < P_; p++) {
                float v = acc8[p] * scale;
                v = (v > 0.0f) ? v : 0.1f * v;
                orow[x0 + p] = v;
            }
        }

        __syncthreads();   // finish reads before rebinding smem to next row
    }
}

extern "C" void kernel_launch(void* const* d_in, const int* in_sizes, int n_in,
                              void* d_out, int out_size)
{
    const float* feat1 = (const float*)d_in[0];
    const float* feat2 = (const float*)d_in[1];
    float* out = (float*)d_out;
    cudaFuncSetAttribute(corr_leaky_kernel,
                         cudaFuncAttributeMaxDynamicSharedMemorySize, SMEM_BYTES);
    reset_ctr_kernel<<<1, 1>>>();
    corr_leaky_kernel<<<NBLOCKS, NTHREADS, SMEM_BYTES>>>(feat1, feat2, out);
}

// round 10
// speedup vs baseline: 1.0789x; 1.0789x over previous
#include <cuda_runtime.h>

// PWC-Net correlation (MAX_DISP=4 -> 81 channels) + LeakyReLU(0.1), /C normalize.
// feat1, feat2: [N=8, C=256, H=80, W=160] fp32. out: [N, 81, H, W] fp32.
//
// R6: cp.async double-buffer -> 250us. R7: persistent grid -> 232us.
// R8: FFMA2 packing REGRESSED (242us): f32x2 costs the same fma-pipe cycles as
//     2x FFMA on sm_103a; packing movs were pure overhead. Reverted.
// R9: occupancy 2 -> 3 CTAs/SM. R7 ncu: no pipe >59% (issue 59, L1 55, fma 25)
//     -> latency-bound at 4.5 warps/SMSP. launch_bounds(288,3) caps regs at 75
//     (live set ~71: 45 acc + 18 operands + addrs); grid 444 persistent.

#define MAXD 4
#define DD   9
#define NCH  81
#define C_   256
#define H_   80
#define W_   160
#define N_   8
#define HW_  (H_ * W_)
#define NROWS (N_ * H_)      // 640 work units (one per (n,y))
#define CC   4
#define P_   5
#define F2W  (W_ + 2*MAXD)   // 168
#define NQ4  (F2W / 4)       // 42
#define NTHREADS (DD * 32)   // 288
#define NCHUNK (C_ / CC)     // 64
#define NBLOCKS (148 * 3)    // 444 = 3 CTAs per SM

#define S1_FLOATS (2 * CC * W_)
#define S2_FLOATS (2 * CC * DD * F2W)
#define SMEM_BYTES ((S1_FLOATS + S2_FLOATS) * 4)  // 53504 B -> 160.5KB/SM at occ 3

__device__ int g_row_ctr;
__global__ void reset_ctr_kernel() { g_row_ctr = 0; }

__device__ __forceinline__ void cp16(float* dst_smem, const float* src_gmem) {
    unsigned d = (unsigned)__cvta_generic_to_shared(dst_smem);
    asm volatile("cp.async.cg.shared.global [%0], [%1], 16;" :: "r"(d), "l"(src_gmem));
}
#define CP_COMMIT() asm volatile("cp.async.commit_group;")
#define CP_WAIT0()  asm volatile("cp.async.wait_group 0;" ::: "memory")

__global__ __launch_bounds__(NTHREADS, 3)
void corr_leaky_kernel(const float* __restrict__ f1,
                       const float* __restrict__ f2,
                       float* __restrict__ out)
{
    extern __shared__ __align__(16) float smem[];
    float* s1 = smem;               // [2][CC][W_]
    float* s2 = smem + S1_FLOATS;   // [2][CC][DD][F2W]
#define S1REF(b,c,x)   s1[((b)*CC + (c))*W_ + (x)]
#define S2REF(b,c,r,j) s2[(((b)*CC + (c))*DD + (r))*F2W + (j)]
    __shared__ int s_row;

    const int tid  = threadIdx.x;
    const int dy   = tid >> 5;
    const int lane = tid & 31;
    const int x0   = lane * P_;

    // f1 staging: one float4 per thread for tid < 160
    const int f1c  = tid / 40;
    const int f1j4 = tid - f1c * 40;
    const bool f1ok = (tid < CC * (W_ / 4));

    const float scale = 1.0f / (float)C_;

    for (;;) {
        // ---- grab next row ----
        if (tid == 0) s_row = atomicAdd(&g_row_ctr, 1);
        __syncthreads();
        const int row = s_row;
        __syncthreads();           // s_row consumed before next overwrite
        if (row >= NROWS) break;

        const int n = row / H_;
        const int y = row - n * H_;

        const int img_base = n * C_ * HW_;
        const int  gy    = y + dy - MAXD;
        const bool rowok = ((unsigned)gy < (unsigned)H_);
        const float* f1base = f1 + img_base + y * W_;
        const float* f2base = f2 + img_base + gy * W_;

        // ---- set pad slots (fixed border positions) in BOTH buffers ----
        const float4 z4 = make_float4(0.f, 0.f, 0.f, 0.f);
#pragma unroll
        for (int b = 0; b < 2; b++)
#pragma unroll
            for (int c = 0; c < CC; c++) {
                if (rowok) {
                    if (lane == 0) *(float4*)&S2REF(b, c, dy, 0) = z4;
                    if (lane == 1) *(float4*)&S2REF(b, c, dy, 4 * (NQ4 - 1)) = z4;
                } else {
                    *(float4*)&S2REF(b, c, dy, 4 * lane) = z4;
                    if (lane < NQ4 - 32) *(float4*)&S2REF(b, c, dy, 4 * (32 + lane)) = z4;
                }
            }

        float acc[P_][DD];
#pragma unroll
        for (int p = 0; p < P_; p++)
#pragma unroll
            for (int dx = 0; dx < DD; dx++) acc[p][dx] = 0.0f;

        // ---- prologue: prefetch chunk 0 into buffer 0 ----
        if (f1ok) cp16(&S1REF(0, f1c, 4 * f1j4), f1base + f1c * HW_ + 4 * f1j4);
        if (rowok) {
#pragma unroll
            for (int c = 0; c < CC; c++) {
                const float* rowp = f2base + c * HW_;
                if (lane >= 1) cp16(&S2REF(0, c, dy, 4 * lane),        rowp + 4 * lane - 4);
                if (lane <= 8) cp16(&S2REF(0, c, dy, 4 * (32 + lane)), rowp + 4 * (32 + lane) - 4);
            }
        }
        CP_COMMIT();

        for (int i = 0; i < NCHUNK; i++) {
            const int cur = i & 1;
            CP_WAIT0();
            __syncthreads();

            if (i + 1 < NCHUNK) {
                const int nb = cur ^ 1;
                const int c0 = (i + 1) * CC;
                if (f1ok) cp16(&S1REF(nb, f1c, 4 * f1j4),
                               f1base + (c0 + f1c) * HW_ + 4 * f1j4);
                if (rowok) {
#pragma unroll
                    for (int c = 0; c < CC; c++) {
                        const float* rowp = f2base + (c0 + c) * HW_;
                        if (lane >= 1) cp16(&S2REF(nb, c, dy, 4 * lane),        rowp + 4 * lane - 4);
                        if (lane <= 8) cp16(&S2REF(nb, c, dy, 4 * (32 + lane)), rowp + 4 * (32 + lane) - 4);
                    }
                }
                CP_COMMIT();
            }

            // ---- compute on buf[cur]: per channel 18 LDS feed 45 FFMA ----
#pragma unroll
            for (int cc = 0; cc < CC; cc++) {
                float a[P_];
                float b[P_ + DD - 1];
#pragma unroll
                for (int p = 0; p < P_; p++) a[p] = S1REF(cur, cc, x0 + p);
#pragma unroll
                for (int k = 0; k < P_ + DD - 1; k++) b[k] = S2REF(cur, cc, dy, x0 + k);
#pragma unroll
                for (int p = 0; p < P_; p++)
#pragma unroll
                    for (int dx = 0; dx < DD; dx++)
                        acc[p][dx] = fmaf(a[p], b[p + dx], acc[p][dx]);
            }
        }

        // ---- epilogue: /C, LeakyReLU(0.1), store ----
        const int out_base = n * NCH * HW_ + y * W_;
#pragma unroll
        for (int dx = 0; dx < DD; dx++) {
            const int ch = dy * DD + dx;
            float* orow = out + out_base + ch * HW_;
#pragma unroll
            for (int p = 0; p < P_; p++) {
                float v = acc[p][dx] * scale;
                v = (v > 0.0f) ? v : 0.1f * v;
                orow[x0 + p] = v;
            }
        }

        __syncthreads();   // all reads of this row's smem done before rebinding
    }
}

extern "C" void kernel_launch(void* const* d_in, const int* in_sizes, int n_in,
                              void* d_out, int out_size)
{
    const float* feat1 = (const float*)d_in[0];
    const float* feat2 = (const float*)d_in[1];
    float* out = (float*)d_out;
    cudaFuncSetAttribute(corr_leaky_kernel,
                         cudaFuncAttributeMaxDynamicSharedMemorySize, SMEM_BYTES);
    reset_ctr_kernel<<<1, 1>>>();
    corr_leaky_kernel<<<NBLOCKS, NTHREADS, SMEM_BYTES>>>(feat1, feat2, out);
}

// round 11
// speedup vs baseline: 1.1372x; 1.0540x over previous
#include <cuda_runtime.h>

// PWC-Net correlation (MAX_DISP=4 -> 81 channels) + LeakyReLU(0.1), /C normalize.
// feat1, feat2: [N=8, C=256, H=80, W=160] fp32. out: [N, 81, H, W] fp32.
//
// R7: persistent grid 232us. R8: FFMA2 regressed (same fma cycles), reverted.
// R9: occ 3 (regs 72) -> 224.7us; issue 66%, L1 57%, fma 26% -> ~25% of issue
//     slots are addressing/overhead.
// R10: issue-slot diet: unroll-2 chunk loop (const-folds buffer parity),
//      b-streaming inner loop (live-b=1, hoisted row pointers), one less
//      barrier per row. Counts unchanged: 18 LDS + 45 FFMA per channel.

#define MAXD 4
#define DD   9
#define NCH  81
#define C_   256
#define H_   80
#define W_   160
#define N_   8
#define HW_  (H_ * W_)
#define NROWS (N_ * H_)
#define CC   4
#define P_   5
#define F2W  (W_ + 2*MAXD)   // 168
#define NQ4  (F2W / 4)       // 42
#define NTHREADS (DD * 32)   // 288
#define NCHUNK (C_ / CC)     // 64
#define NBLOCKS (148 * 3)    // 444 persistent blocks, 3 CTAs/SM

#define S1_FLOATS (2 * CC * W_)
#define S2_FLOATS (2 * CC * DD * F2W)
#define SMEM_BYTES ((S1_FLOATS + S2_FLOATS) * 4)  // 53504 B

__device__ int g_row_ctr;
__global__ void reset_ctr_kernel() { g_row_ctr = 0; }

__device__ __forceinline__ void cp16(float* dst_smem, const float* src_gmem) {
    unsigned d = (unsigned)__cvta_generic_to_shared(dst_smem);
    asm volatile("cp.async.cg.shared.global [%0], [%1], 16;" :: "r"(d), "l"(src_gmem));
}
#define CP_COMMIT() asm volatile("cp.async.commit_group;")
#define CP_WAIT0()  asm volatile("cp.async.wait_group 0;" ::: "memory")

__global__ __launch_bounds__(NTHREADS, 3)
void corr_leaky_kernel(const float* __restrict__ f1,
                       const float* __restrict__ f2,
                       float* __restrict__ out)
{
    extern __shared__ __align__(16) float smem[];
    float* s1 = smem;               // [2][CC][W_]
    float* s2 = smem + S1_FLOATS;   // [2][CC][DD][F2W]
#define S1REF(b,c,x)   s1[((b)*CC + (c))*W_ + (x)]
#define S2REF(b,c,r,j) s2[(((b)*CC + (c))*DD + (r))*F2W + (j)]
    __shared__ int s_row;

    const int tid  = threadIdx.x;
    const int dy   = tid >> 5;
    const int lane = tid & 31;
    const int x0   = lane * P_;

    const int f1c  = tid / 40;
    const int f1j4 = tid - f1c * 40;
    const bool f1ok = (tid < CC * (W_ / 4));

    const float scale = 1.0f / (float)C_;

    // hoisted per-thread smem row pointers (buffer parity resolved at compile
    // time inside the unrolled chunk loop)
    // s1 row for this thread's pixels; s2 row dy for this warp.

    for (;;) {
        if (tid == 0) s_row = atomicAdd(&g_row_ctr, 1);
        __syncthreads();
        const int row = s_row;       // end-of-body sync orders the next rewrite
        if (row >= NROWS) break;

        const int n = row / H_;
        const int y = row - n * H_;

        const int img_base = n * C_ * HW_;
        const int  gy    = y + dy - MAXD;
        const bool rowok = ((unsigned)gy < (unsigned)H_);
        const float* f1base = f1 + img_base + y * W_;
        const float* f2base = f2 + img_base + gy * W_;

        // pad slots (fixed border positions) in BOTH buffers
        const float4 z4 = make_float4(0.f, 0.f, 0.f, 0.f);
#pragma unroll
        for (int b = 0; b < 2; b++)
#pragma unroll
            for (int c = 0; c < CC; c++) {
                if (rowok) {
                    if (lane == 0) *(float4*)&S2REF(b, c, dy, 0) = z4;
                    if (lane == 1) *(float4*)&S2REF(b, c, dy, 4 * (NQ4 - 1)) = z4;
                } else {
                    *(float4*)&S2REF(b, c, dy, 4 * lane) = z4;
                    if (lane < NQ4 - 32) *(float4*)&S2REF(b, c, dy, 4 * (32 + lane)) = z4;
                }
            }

        float acc[P_][DD];
#pragma unroll
        for (int p = 0; p < P_; p++)
#pragma unroll
            for (int dx = 0; dx < DD; dx++) acc[p][dx] = 0.0f;

        // prologue: prefetch chunk 0 into buffer 0
        if (f1ok) cp16(&S1REF(0, f1c, 4 * f1j4), f1base + f1c * HW_ + 4 * f1j4);
        if (rowok) {
#pragma unroll
            for (int c = 0; c < CC; c++) {
                const float* rowp = f2base + c * HW_;
                if (lane >= 1) cp16(&S2REF(0, c, dy, 4 * lane),        rowp + 4 * lane - 4);
                if (lane <= 8) cp16(&S2REF(0, c, dy, 4 * (32 + lane)), rowp + 4 * (32 + lane) - 4);
            }
        }
        CP_COMMIT();

#pragma unroll 2
        for (int i = 0; i < NCHUNK; i++) {
            const int cur = i & 1;           // compile-time under unroll 2
            CP_WAIT0();
            __syncthreads();

            if (i + 1 < NCHUNK) {
                const int nb = cur ^ 1;
                const int c0 = (i + 1) * CC;
                if (f1ok) cp16(&S1REF(nb, f1c, 4 * f1j4),
                               f1base + (c0 + f1c) * HW_ + 4 * f1j4);
                if (rowok) {
#pragma unroll
                    for (int c = 0; c < CC; c++) {
                        const float* rowp = f2base + (c0 + c) * HW_;
                        if (lane >= 1) cp16(&S2REF(nb, c, dy, 4 * lane),        rowp + 4 * lane - 4);
                        if (lane <= 8) cp16(&S2REF(nb, c, dy, 4 * (32 + lane)), rowp + 4 * (32 + lane) - 4);
                    }
                }
                CP_COMMIT();
            }

            // compute on buf[cur]: b-streaming — load b[k] once, feed its <=5 FFMAs
#pragma unroll
            for (int cc = 0; cc < CC; cc++) {
                const float* s1row = &S1REF(cur, cc, x0);
                const float* s2row = &S2REF(cur, cc, dy, x0);
                float a[P_];
#pragma unroll
                for (int p = 0; p < P_; p++) a[p] = s1row[p];
#pragma unroll
                for (int k = 0; k < P_ + DD - 1; k++) {
                    const float bk = s2row[k];
                    const int plo = (k - (DD - 1)) > 0 ? (k - (DD - 1)) : 0;
                    const int phi = k < (P_ - 1) ? k : (P_ - 1);
#pragma unroll
                    for (int p = plo; p <= phi; p++)
                        acc[p][k - p] = fmaf(a[p], bk, acc[p][k - p]);
                }
            }
        }

        // epilogue: /C, LeakyReLU(0.1), store
        const int out_base = n * NCH * HW_ + y * W_;
#pragma unroll
        for (int dx = 0; dx < DD; dx++) {
            const int ch = dy * DD + dx;
            float* orow = out + out_base + ch * HW_;
#pragma unroll
            for (int p = 0; p < P_; p++) {
                float v = acc[p][dx] * scale;
                v = (v > 0.0f) ? v : 0.1f * v;
                orow[x0 + p] = v;
            }
        }

        __syncthreads();   // orders smem rebind AND s_row rewrite for next iter
    }
}

extern "C" void kernel_launch(void* const* d_in, const int* in_sizes, int n_in,
                              void* d_out, int out_size)
{
    const float* feat1 = (const float*)d_in[0];
    const float* feat2 = (const float*)d_in[1];
    float* out = (float*)d_out;
    cudaFuncSetAttribute(corr_leaky_kernel,
                         cudaFuncAttributeMaxDynamicSharedMemorySize, SMEM_BYTES);
    reset_ctr_kernel<<<1, 1>>>();
    corr_leaky_kernel<<<NBLOCKS, NTHREADS, SMEM_BYTES>>>(feat1, feat2, out);
}